// round 17
// baseline (speedup 1.0000x reference)
#include <cuda_runtime.h>
#include <cuda_bf16.h>
#include <math.h>
#include <stdint.h>

// Problem constants
#define BB 2
#define NN 2048
#define BN 4096          // B*N
#define CC 256
#define HI 64
#define WI 176
#define HW (HI*WI)       // 11264
#define TS 16            // tile size
#define TBX (WI/TS)      // 11
#define TBY (HI/TS)      // 4
#define TPB (TBX*TBY)    // 44 tiles per batch
#define NT (BB*TPB)      // 88 tiles total
#define MAXG 2048
#define FM_SIZE (BB*CC*HW)
#define NSL 8            // render channel slices
#define CPS 32           // channels per slice

// ---------------- device scratch ----------------
__device__ uint32_t a_gh[BN*8], a_gl[BN*8];       // input g (K=14 -> 8 pairs padded)
__device__ uint32_t w1h[8*64],    w1l[8*64];
__device__ uint32_t w2h[32*128],  w2l[32*128];
__device__ uint32_t w3h[64*256],  w3l[64*256];
__device__ uint32_t f1h[128*256], f1l[128*256];
__device__ uint32_t f2h[128*256], f2l[128*256];

__device__ float g_featsT[BN*CC];
__device__ float g_px[BN], g_py[BN], g_isx[BN], g_isy[BN], g_w[BN], g_as[BN];
__device__ int   g_tcount[NT];
__device__ int   g_tlist[NT*MAXG];

// ---------------- bf16 helpers ----------------
__device__ __forceinline__ void bfsplit(float x, __nv_bfloat16& h, __nv_bfloat16& l) {
    h = __float2bfloat16(x);
    l = __float2bfloat16(x - __bfloat162float(h));
}
__device__ __forceinline__ uint32_t pkbf(__nv_bfloat16 lo, __nv_bfloat16 hi) {
    __nv_bfloat162 v = __halves2bfloat162(lo, hi);
    return *(uint32_t*)&v;
}
__device__ __forceinline__ void mma_bf16(float* c,
    uint32_t a0, uint32_t a1, uint32_t a2, uint32_t a3,
    uint32_t b0, uint32_t b1)
{
    asm("mma.sync.aligned.m16n8k16.row.col.f32.bf16.bf16.f32 "
        "{%0,%1,%2,%3}, {%4,%5,%6,%7}, {%8,%9}, {%0,%1,%2,%3};"
        : "+f"(c[0]), "+f"(c[1]), "+f"(c[2]), "+f"(c[3])
        : "r"(a0), "r"(a1), "r"(a2), "r"(a3), "r"(b0), "r"(b1));
}

// ---------------- single fused prep: split input + ALL weights --------------
#define PREP_TOTAL 119296
__device__ __forceinline__ void split_w_elem(const float* __restrict__ W,
    uint32_t* __restrict__ Wh, uint32_t* __restrict__ Wl,
    int local, int Kd, int Nd)
{
    int k2 = local / Nd, n = local - k2 * Nd;
    float v0 = (2 * k2     < Kd) ? W[(size_t)(2 * k2)     * Nd + n] : 0.f;
    float v1 = (2 * k2 + 1 < Kd) ? W[(size_t)(2 * k2 + 1) * Nd + n] : 0.f;
    __nv_bfloat16 h0, l0, h1, l1;
    bfsplit(v0, h0, l0); bfsplit(v1, h1, l1);
    Wh[local] = pkbf(h0, h1);
    Wl[local] = pkbf(l0, l1);
}

__global__ void prep_all(const float* __restrict__ g,
                         const float* __restrict__ W1, const float* __restrict__ W2,
                         const float* __restrict__ W3, const float* __restrict__ F1,
                         const float* __restrict__ F2)
{
    int idx = blockIdx.x * blockDim.x + threadIdx.x;
    if (idx >= PREP_TOTAL) return;
    if (idx < 32768) {
        int row = idx >> 3, k2 = idx & 7;
        float v0 = (2 * k2     < 14) ? g[(size_t)row * 14 + 2 * k2]     : 0.f;
        float v1 = (2 * k2 + 1 < 14) ? g[(size_t)row * 14 + 2 * k2 + 1] : 0.f;
        __nv_bfloat16 h0, l0, h1, l1;
        bfsplit(v0, h0, l0); bfsplit(v1, h1, l1);
        a_gh[idx] = pkbf(h0, h1);
        a_gl[idx] = pkbf(l0, l1);
    } else if (idx < 33280) {
        split_w_elem(W1, w1h, w1l, idx - 32768, 14, 64);
    } else if (idx < 37376) {
        split_w_elem(W2, w2h, w2l, idx - 33280, 64, 128);
    } else if (idx < 53760) {
        split_w_elem(W3, w3h, w3l, idx - 37376, 128, 256);
    } else if (idx < 86528) {
        split_w_elem(F1, f1h, f1l, idx - 53760, 256, 256);
    } else {
        split_w_elem(F2, f2h, f2l, idx - 86528, 256, 256);
    }
}

// ---------------- projection + binning (fused) ----------------
__global__ void proj_bin_kernel(const float* __restrict__ g, const float* __restrict__ Kin) {
    int i = blockIdx.x * blockDim.x + threadIdx.x;
    if (i >= BN) return;
    const float* gd = g + (size_t)i * 14;
    float x = gd[0], y = gd[1], z = gd[2];
    float k00 = Kin[0], k01 = Kin[1], k02 = Kin[2];
    float k10 = Kin[3], k11 = Kin[4], k12 = Kin[5];
    float k20 = Kin[6], k21 = Kin[7], k22 = Kin[8];
    float pz = k20 * x + k21 * y + k22 * z;
    float denom = pz + 1e-6f;
    float pxn = (k00 * x + k01 * y + k02 * z) / denom;
    float pyn = (k10 * x + k11 * y + k12 * z) / denom;
    float scale_x = (float)WI / k02 * 0.5f;
    float scale_y = (float)HI / k12 * 0.5f;
    float px = pxn * scale_x;
    float py = pyn * scale_y;
    bool valid = (z > 0.1f);
    bool inb = (px >= 0.f) && (px < (float)WI) && (py >= 0.f) && (py < (float)HI);
    bool mask = valid && inb;
    float sx = fmaxf(gd[5] * scale_x, 1.0f);
    float sy = fmaxf(gd[6] * scale_y, 1.0f);
    float w = mask ? gd[12] : 0.0f;
    g_px[i] = px;  g_py[i] = py;
    g_isx[i] = 1.0f / sx;  g_isy[i] = 1.0f / sy;
    g_w[i]  = w;
    g_as[i] = 0.5f * (sx + sy);
    if (w == 0.0f) return;

    float rx = 3.0f * sx;
    float ry = 3.0f * sy;
    int b = i >> 11;
    int tx0 = max(0, (int)floorf((px - rx) * (1.0f / TS)));
    int tx1 = min(TBX - 1, (int)floorf((px + rx) * (1.0f / TS)));
    int ty0 = max(0, (int)floorf((py - ry) * (1.0f / TS)));
    int ty1 = min(TBY - 1, (int)floorf((py + ry) * (1.0f / TS)));
    for (int ty = ty0; ty <= ty1; ty++)
        for (int tx = tx0; tx <= tx1; tx++) {
            int t = b * TPB + ty * TBX + tx;
            int o = atomicAdd(&g_tcount[t], 1);
            if (o < MAXG) g_tlist[t * MAXG + o] = i;
        }
}

// ---------------- fused MLP: all 5 layers in one kernel (R16, unchanged) ----
#define ACT_STRIDE 40
#define WB_STRIDE 264
#define SM_A0H 0
#define SM_A0L 5120
#define SM_A1H 10240
#define SM_A1L 15360
#define SM_WBH 20480
#define SM_WBL 24704
#define MLP_SMEM_U32 28928
#define MLP_SMEM_BYTES (MLP_SMEM_U32 * 4)

template<int K2IN, int N, bool RELU, bool LAST>
__device__ __forceinline__ void mlp_layer(
    const uint32_t* __restrict__ aih, const uint32_t* __restrict__ ail,
    uint32_t* __restrict__ aoh, uint32_t* __restrict__ aol,
    uint32_t* __restrict__ wbh, uint32_t* __restrict__ wbl,
    const uint32_t* __restrict__ Wh, const uint32_t* __restrict__ Wl,
    const float* __restrict__ bias, float* __restrict__ outF,
    int m0, int t)
{
    constexpr int NKT = K2IN / 8;
    constexpr int CNT = N / 32;
    int lane = t & 31, wid = t >> 5;
    int wm = wid & 1, wn = wid >> 1;
    int g = lane >> 2, c = lane & 3;

    float d[CNT][4];
    #pragma unroll
    for (int nt = 0; nt < CNT; nt++)
        #pragma unroll
        for (int i = 0; i < 4; i++) d[nt][i] = 0.f;

    int wrow = t >> 5;
    int wcol = (t & 31) * CNT;

    uint32_t wrh[CNT], wrl[CNT];
    {
        const uint32_t* ph = &Wh[(size_t)wrow * N + wcol];
        const uint32_t* pl = &Wl[(size_t)wrow * N + wcol];
        #pragma unroll
        for (int i = 0; i < CNT; i += 2) {
            uint2 vh = *(const uint2*)(ph + i); wrh[i] = vh.x; wrh[i + 1] = vh.y;
            uint2 vl = *(const uint2*)(pl + i); wrl[i] = vl.x; wrl[i + 1] = vl.y;
        }
    }

    for (int kt = 0; kt < NKT; kt++) {
        int buf = kt & 1;
        uint32_t* sh = wbh + buf * 2112 + wrow * WB_STRIDE + wcol;
        uint32_t* sl = wbl + buf * 2112 + wrow * WB_STRIDE + wcol;
        #pragma unroll
        for (int i = 0; i < CNT; i += 2) {
            *(uint2*)(sh + i) = make_uint2(wrh[i], wrh[i + 1]);
            *(uint2*)(sl + i) = make_uint2(wrl[i], wrl[i + 1]);
        }
        __syncthreads();
        if (kt + 1 < NKT) {
            const uint32_t* ph = &Wh[(size_t)((kt + 1) * 8 + wrow) * N + wcol];
            const uint32_t* pl = &Wl[(size_t)((kt + 1) * 8 + wrow) * N + wcol];
            #pragma unroll
            for (int i = 0; i < CNT; i += 2) {
                uint2 vh = *(const uint2*)(ph + i); wrh[i] = vh.x; wrh[i + 1] = vh.y;
                uint2 vl = *(const uint2*)(pl + i); wrl[i] = vl.x; wrl[i + 1] = vl.y;
            }
        }
        int m = wm * 16 + g;
        uint32_t ah0 = aih[(kt * 8 + c) * ACT_STRIDE + m];
        uint32_t ah1 = aih[(kt * 8 + c) * ACT_STRIDE + m + 8];
        uint32_t ah2 = aih[(kt * 8 + c + 4) * ACT_STRIDE + m];
        uint32_t ah3 = aih[(kt * 8 + c + 4) * ACT_STRIDE + m + 8];
        uint32_t al0 = ail[(kt * 8 + c) * ACT_STRIDE + m];
        uint32_t al1 = ail[(kt * 8 + c) * ACT_STRIDE + m + 8];
        uint32_t al2 = ail[(kt * 8 + c + 4) * ACT_STRIDE + m];
        uint32_t al3 = ail[(kt * 8 + c + 4) * ACT_STRIDE + m + 8];
        const uint32_t* bh_s = wbh + buf * 2112;
        const uint32_t* bl_s = wbl + buf * 2112;
        #pragma unroll
        for (int nt = 0; nt < CNT; nt++) {
            int n = wn * (N / 4) + nt * 8 + g;
            uint32_t b0h = bh_s[c * WB_STRIDE + n];
            uint32_t b1h = bh_s[(c + 4) * WB_STRIDE + n];
            uint32_t b0l = bl_s[c * WB_STRIDE + n];
            uint32_t b1l = bl_s[(c + 4) * WB_STRIDE + n];
            mma_bf16(d[nt], ah0, ah1, ah2, ah3, b0h, b1h);
            mma_bf16(d[nt], al0, al1, al2, al3, b0h, b1h);
            mma_bf16(d[nt], ah0, ah1, ah2, ah3, b0l, b1l);
        }
    }

    #pragma unroll
    for (int nt = 0; nt < CNT; nt++) {
        int col = wn * (N / 4) + nt * 8 + c * 2;
        float2 bv = *(const float2*)&bias[col];
        int row0 = wm * 16 + g;
        float o0 = d[nt][0] + bv.x, o1 = d[nt][1] + bv.y;
        float o2 = d[nt][2] + bv.x, o3 = d[nt][3] + bv.y;
        if (RELU) {
            o0 = fmaxf(o0, 0.f); o1 = fmaxf(o1, 0.f);
            o2 = fmaxf(o2, 0.f); o3 = fmaxf(o3, 0.f);
        }
        if (LAST) {
            *(float2*)&outF[(size_t)(m0 + row0) * CC + col]     = make_float2(o0, o1);
            *(float2*)&outF[(size_t)(m0 + row0 + 8) * CC + col] = make_float2(o2, o3);
        } else {
            int colp = col >> 1;
            __nv_bfloat16 h0, l0, h1, l1;
            bfsplit(o0, h0, l0); bfsplit(o1, h1, l1);
            aoh[colp * ACT_STRIDE + row0] = pkbf(h0, h1);
            aol[colp * ACT_STRIDE + row0] = pkbf(l0, l1);
            bfsplit(o2, h0, l0); bfsplit(o3, h1, l1);
            aoh[colp * ACT_STRIDE + row0 + 8] = pkbf(h0, h1);
            aol[colp * ACT_STRIDE + row0 + 8] = pkbf(l0, l1);
        }
    }
    __syncthreads();
}

__global__ void __launch_bounds__(256) fused_mlp(
    const float* __restrict__ b1, const float* __restrict__ b2,
    const float* __restrict__ b3, const float* __restrict__ fb1,
    const float* __restrict__ fb2)
{
    extern __shared__ uint32_t sm[];
    uint32_t* A0h = sm + SM_A0H;
    uint32_t* A0l = sm + SM_A0L;
    uint32_t* A1h = sm + SM_A1H;
    uint32_t* A1l = sm + SM_A1L;
    uint32_t* WBh = sm + SM_WBH;
    uint32_t* WBl = sm + SM_WBL;
    int t = threadIdx.x;
    int m0 = blockIdx.x * 32;

    {
        int m = t & 31, k2 = t >> 5;
        A0h[k2 * ACT_STRIDE + m] = a_gh[(size_t)(m0 + m) * 8 + k2];
        A0l[k2 * ACT_STRIDE + m] = a_gl[(size_t)(m0 + m) * 8 + k2];
    }
    __syncthreads();

    mlp_layer<8,   64,  true,  false>(A0h, A0l, A1h, A1l, WBh, WBl, w1h, w1l, b1,  nullptr,  m0, t);
    mlp_layer<32,  128, true,  false>(A1h, A1l, A0h, A0l, WBh, WBl, w2h, w2l, b2,  nullptr,  m0, t);
    mlp_layer<64,  256, false, false>(A0h, A0l, A1h, A1l, WBh, WBl, w3h, w3l, b3,  nullptr,  m0, t);
    mlp_layer<128, 256, true,  false>(A1h, A1l, A0h, A0l, WBh, WBl, f1h, f1l, fb1, nullptr,  m0, t);
    mlp_layer<128, 256, false, true >(A0h, A0l, A1h, A1l, WBh, WBl, f2h, f2l, fb2, g_featsT, m0, t);
}

// ---------------- tile render: 8 slices x 32 ch, bf16 2-split MMA -------------
// grid (NT, 8), 256 threads = 8 warps in 2(ch: 16 each) x 4(px: 64 each).
// Per 16-gaussian batch: one k16 slab, 1 mt x 8 nt x 3 MMAs per warp.
__global__ void __launch_bounds__(256) render_kernel(float* __restrict__ out) {
    int tile = blockIdx.x;
    int slice = blockIdx.y;
    int b = tile / TPB;
    int tl = tile % TPB;
    int tx0 = (tl % TBX) * TS;
    int ty0 = (tl / TBX) * TS;
    int t = threadIdx.x;
    int lx = t & 15;
    int ly = t >> 4;
    int lane = t & 31;
    int wid = t >> 5;
    int wm = wid & 1;        // 2 warps in channels (16 each)
    int wn = wid >> 1;       // 4 warps in pixels (64 each)
    int g = lane >> 2;
    int c = lane & 3;

    __shared__ float s_px[16], s_py[16], s_isx[16], s_isy[16], s_w[16], s_as[16];
    __shared__ int   s_n[16];
    __shared__ float s_dx2[16][16], s_dy2[16][16], s_ex[16][16], s_ey[16][16];
    __shared__ uint32_t s_gwh[8][264], s_gwl[8][264];   // [j2][pixel] bf16 pairs
    __shared__ uint32_t s_Fh[8][40], s_Fl[8][40];       // [j2][ch] pairs (32ch + pad)

    float* s_d = &s_dx2[0][0];   // reused for density after main loop

    float d[8][4];   // 8 nt (64 px) x frag; 16 channels (rows g, g+8)
    #pragma unroll
    for (int nt = 0; nt < 8; nt++)
        #pragma unroll
        for (int i = 0; i < 4; i++) d[nt][i] = 0.f;
    float dacc = 0.f, uacc = 0.f;

    int K = g_tcount[tile];
    if (K > MAXG) K = MAXG;

    for (int c0 = 0; c0 < K; c0 += 16) {
        if (t < 16) {
            int idx = c0 + t;
            if (idx < K) {
                int n = g_tlist[tile * MAXG + idx];
                s_n[t] = n;
                s_px[t] = g_px[n];   s_py[t] = g_py[n];
                s_isx[t] = g_isx[n]; s_isy[t] = g_isy[n];
                s_w[t] = g_w[n];     s_as[t] = g_as[n];
            } else {
                s_n[t] = 0;
                s_px[t] = 3e8f; s_py[t] = 3e8f;
                s_isx[t] = 1.f; s_isy[t] = 1.f;
                s_w[t] = 0.f;   s_as[t] = 0.f;
            }
        }
        __syncthreads();
        // F slice: 16 gaussians x 32 channels -> bf16 pairs along j
        // 256 threads: j2 = t>>5 (0..7), ch = t&31 (one channel each)
        {
            int j2 = t >> 5;
            int ch = t & 31;
            int ne = s_n[2 * j2], no = s_n[2 * j2 + 1];
            float fe = g_featsT[(size_t)ne * CC + slice * CPS + ch];
            float fo = g_featsT[(size_t)no * CC + slice * CPS + ch];
            __nv_bfloat162 h2 = __floats2bfloat162_rn(fe, fo);
            float2 hf = __bfloat1622float2(h2);
            __nv_bfloat162 l2 = __floats2bfloat162_rn(fe - hf.x, fo - hf.y);
            s_Fh[j2][ch] = *(uint32_t*)&h2;
            s_Fl[j2][ch] = *(uint32_t*)&l2;
        }
        // separable exp
        {
            int j = t >> 4, i2 = t & 15;
            float dx = ((float)(tx0 + i2) - s_px[j]) * s_isx[j];
            float dx2 = dx * dx;
            s_dx2[j][i2] = dx2;
            s_ex[j][i2] = __expf(-0.5f * dx2);
            float dy = ((float)(ty0 + i2) - s_py[j]) * s_isy[j];
            float dy2 = dy * dy;
            s_dy2[j][i2] = dy2;
            s_ey[j][i2] = __expf(-0.5f * dy2);
        }
        __syncthreads();
        // gw for my pixel across 16 gaussians (exact fp32 density)
        #pragma unroll
        for (int j2 = 0; j2 < 8; j2++) {
            int j0 = 2 * j2, j1 = 2 * j2 + 1;
            float dd0 = s_dx2[j0][lx] + s_dy2[j0][ly];
            float dd1 = s_dx2[j1][lx] + s_dy2[j1][ly];
            float g0 = (dd0 < 9.0f) ? s_w[j0] * s_ex[j0][lx] * s_ey[j0][ly] : 0.0f;
            float g1 = (dd1 < 9.0f) ? s_w[j1] * s_ex[j1][lx] * s_ey[j1][ly] : 0.0f;
            dacc += g0 + g1;
            uacc += g0 * s_as[j0] + g1 * s_as[j1];
            __nv_bfloat162 h2 = __floats2bfloat162_rn(g0, g1);
            float2 hf = __bfloat1622float2(h2);
            __nv_bfloat162 l2 = __floats2bfloat162_rn(g0 - hf.x, g1 - hf.y);
            s_gwh[j2][t] = *(uint32_t*)&h2;
            s_gwl[j2][t] = *(uint32_t*)&l2;
        }
        __syncthreads();
        // one k16 mma slab: 1 mt x 8 nt x 3 terms per warp
        {
            int m = wm * 16 + g;
            uint32_t ah0 = s_Fh[c][m];     uint32_t ah1 = s_Fh[c][m + 8];
            uint32_t ah2 = s_Fh[c + 4][m]; uint32_t ah3 = s_Fh[c + 4][m + 8];
            uint32_t al0 = s_Fl[c][m];     uint32_t al1 = s_Fl[c][m + 8];
            uint32_t al2 = s_Fl[c + 4][m]; uint32_t al3 = s_Fl[c + 4][m + 8];
            #pragma unroll
            for (int nt = 0; nt < 8; nt++) {
                int n = wn * 64 + nt * 8 + g;
                uint32_t bh0 = s_gwh[c][n],   bh1 = s_gwh[c + 4][n];
                uint32_t bl0 = s_gwl[c][n],   bl1 = s_gwl[c + 4][n];
                mma_bf16(d[nt], ah0, ah1, ah2, ah3, bh0, bh1);
                mma_bf16(d[nt], al0, al1, al2, al3, bh0, bh1);
                mma_bf16(d[nt], ah0, ah1, ah2, ah3, bl0, bl1);
            }
        }
        __syncthreads();
    }

    s_d[t] = dacc;
    __syncthreads();

    // normalize + write: channels ch = slice*32 + wm*16 + g (and +8)
    #pragma unroll
    for (int nt = 0; nt < 8; nt++) {
        int n = wn * 64 + nt * 8 + c * 2;
        float inv0 = 1.0f / fmaxf(s_d[n], 1e-6f);
        float inv1 = 1.0f / fmaxf(s_d[n + 1], 1e-6f);
        int py = n >> 4;
        int pxx = n & 15;
        int ch = slice * CPS + wm * 16 + g;
        float* r0 = out + (((size_t)(b * CC + ch) * HI + ty0 + py) * WI + tx0 + pxx);
        float* r1 = out + (((size_t)(b * CC + ch + 8) * HI + ty0 + py) * WI + tx0 + pxx);
        *(float2*)r0 = make_float2(d[nt][0] * inv0, d[nt][1] * inv1);
        *(float2*)r1 = make_float2(d[nt][2] * inv0, d[nt][3] * inv1);
    }
    if (slice == 0) {
        int pix = (ty0 + ly) * WI + tx0 + lx;
        float dv = fmaxf(dacc, 1e-6f);
        out[FM_SIZE + b * HW + pix] = uacc / dv;
        out[FM_SIZE + BB * HW + b * HW + pix] = dv;
    }
}

// ---------------- launch ----------------
extern "C" void kernel_launch(void* const* d_in, const int* in_sizes, int n_in,
                              void* d_out, int out_size) {
    const float* g      = (const float*)d_in[0];
    const float* intr   = (const float*)d_in[1];
    const float* enc_w1 = (const float*)d_in[2];
    const float* enc_b1 = (const float*)d_in[3];
    const float* enc_w2 = (const float*)d_in[4];
    const float* enc_b2 = (const float*)d_in[5];
    const float* enc_w3 = (const float*)d_in[6];
    const float* enc_b3 = (const float*)d_in[7];
    const float* ft_w1  = (const float*)d_in[8];
    const float* ft_b1  = (const float*)d_in[9];
    const float* ft_w2  = (const float*)d_in[10];
    const float* ft_b2  = (const float*)d_in[11];
    float* out = (float*)d_out;

    int* ptc;
    cudaGetSymbolAddress((void**)&ptc, g_tcount);

    cudaFuncSetAttribute(fused_mlp, cudaFuncAttributeMaxDynamicSharedMemorySize,
                         MLP_SMEM_BYTES);

    cudaMemsetAsync(ptc, 0, NT * sizeof(int));
    prep_all<<<(PREP_TOTAL + 255) / 256, 256>>>(g, enc_w1, enc_w2, enc_w3, ft_w1, ft_w2);
    proj_bin_kernel<<<(BN + 255) / 256, 256>>>(g, intr);
    fused_mlp<<<BN / 32, 256, MLP_SMEM_BYTES>>>(enc_b1, enc_b2, enc_b3, ft_b1, ft_b2);
    render_kernel<<<dim3(NT, NSL), 256>>>(out);
}